// round 7
// baseline (speedup 1.0000x reference)
#include <cuda_runtime.h>
#include <cstdint>

#define CIN   128
#define CHID  256
#define COUT  128
#define HW    1600
#define TP    64
#define NT    512
#define NTILE 25

// SMEM float offsets. Strides: 72 (mod 32 == 8) for x/W2/h, 136 for W1.
#define OXS 0                      // x  [128 c][72]
#define OW1 9216                   // W1 2 x [64 ch][136]
#define OW2 26624                  // W2 2 x [128 oc][72]
#define OHS 45056                  // h  2 x [64 ch][72]
#define OGB 54272                  // gated b2 [128]
#define SMB ((54272 + 128) * 4)    // 217600 B

__device__ float sW1[8 * 4 * 64 * 128];    // tf32-rounded, fragment-permuted, compact
__device__ float sW2[8 * 4 * 128 * 64];
__device__ int   g_idx[256];

__device__ __forceinline__ uint32_t smem_u32(const void* p) {
    uint32_t a;
    asm("{ .reg .u64 t; cvta.to.shared.u64 t, %1; cvt.u32.u64 %0, t; }" : "=r"(a) : "l"(p));
    return a;
}
__device__ __forceinline__ float tf32f(float v) {
    uint32_t r;
    asm("cvt.rna.tf32.f32 %0, %1;" : "=r"(r) : "f"(v));
    return __uint_as_float(r);
}
__device__ __forceinline__ void mma8(float (&d)[4], const float (&a)[4], float b0, float b1) {
    asm("mma.sync.aligned.m16n8k8.row.col.f32.tf32.tf32.f32 "
        "{%0,%1,%2,%3}, {%4,%5,%6,%7}, {%8,%9}, {%0,%1,%2,%3};"
        : "+f"(d[0]), "+f"(d[1]), "+f"(d[2]), "+f"(d[3])
        : "r"(__float_as_uint(a[0])), "r"(__float_as_uint(a[1])),
          "r"(__float_as_uint(a[2])), "r"(__float_as_uint(a[3])),
          "r"(__float_as_uint(b0)),  "r"(__float_as_uint(b1)));
}
#define CPA16(dst, src) asm volatile("cp.async.ca.shared.global [%0], [%1], 16;" :: "r"(dst), "l"(src))
#define CPA_COMMIT()    asm volatile("cp.async.commit_group;" ::: "memory")
#define CPA_WAIT0()     asm volatile("cp.async.wait_group 0;" ::: "memory")

// fragment column permutation: cols (t, t+4) stored adjacently as (2t, 2t+1)
__device__ __forceinline__ int permc(int c) {
    return 8 * (c >> 3) + 2 * (c & 3) + ((c & 4) >> 2);
}

__global__ void prep_idx(const int* __restrict__ raw) {
    __shared__ int odd_nz;
    if (threadIdx.x == 0) odd_nz = 0;
    __syncthreads();
    if (threadIdx.x < 128) {
        if (raw[2 * threadIdx.x + 1] != 0) atomicAdd(&odd_nz, 1);
    }
    __syncthreads();
    bool is64 = (odd_nz == 0);
    g_idx[threadIdx.x] = is64 ? raw[2 * threadIdx.x] : raw[threadIdx.x];
}

__global__ void prep_w(const float* __restrict__ W1, const float* __restrict__ W2) {
    int idx = blockIdx.x * blockDim.x + threadIdx.x;       // 0..262143
    {   // W1[e][256 ch][128 c] -> sW1[(e*4+j)*64+row][128], permuted cols
        int e = idx >> 15, r = (idx >> 7) & 255, c = idx & 127;
        int j = r >> 6, row = r & 63;
        sW1[(size_t)((e * 4 + j) * 64 + row) * 128 + permc(c)] = tf32f(W1[idx]);
    }
    {   // W2[e][128 oc][256 ch] -> sW2[(e*4+j)*128+row][64], permuted cols
        int e = idx >> 15, row = (idx >> 8) & 127, cc = idx & 255;
        int j = cc >> 6, c = cc & 63;
        sW2[(size_t)((e * 4 + j) * 128 + row) * 64 + permc(c)] = tf32f(W2[idx]);
    }
}

__global__ __launch_bounds__(NT, 1)
void moe_tf32(const float* __restrict__ x,
              const float* __restrict__ gate_w,
              const float* __restrict__ b1,
              const float* __restrict__ b2,
              float* __restrict__ out)
{
    extern __shared__ float sm[];
    const uint32_t smb = smem_u32(sm);
    const int tid  = threadIdx.x;
    const int lane = tid & 31;
    const int warp = tid >> 5;
    const int g    = lane >> 2;
    const int t    = lane & 3;
    const int wm   = warp >> 2;        // row group (ch / oc)
    const int wn   = warp & 3;         // px group of 16
    const int b    = blockIdx.y;
    const int p0   = blockIdx.x * TP;

    const int   e0 = g_idx[b * 2],           e1 = g_idx[b * 2 + 1];
    const float g0 = __ldg(&gate_w[b * 2]);
    const float g1 = __ldg(&gate_w[b * 2 + 1]);

    if (tid < 128)
        sm[OGB + tid] = g0 * __ldg(&b2[e0 * COUT + tid]) + g1 * __ldg(&b2[e1 * COUT + tid]);

    // ---- prologue: stage x + W1(0) ----
    {
        const float* xb = x + (size_t)b * CIN * HW + p0;
        #pragma unroll
        for (int i = 0; i < 4; i++) {
            int f = tid + i * NT, row = f >> 4, seg = f & 15;
            CPA16(smb + (uint32_t)(OXS + row * 72 + seg * 4) * 4,
                  xb + (size_t)row * HW + seg * 4);
        }
        const float* w1s = sW1 + (size_t)(e0 * 4) * 8192;
        #pragma unroll
        for (int i = 0; i < 4; i++) {
            int f = tid + i * NT, row = f >> 5, seg = f & 31;
            CPA16(smb + (uint32_t)(OW1 + row * 136 + seg * 4) * 4,
                  w1s + row * 128 + seg * 4);
        }
        CPA_COMMIT();
        CPA_WAIT0();
        // tf32-round own x chunks (thread-local: same mapping as the stage)
        #pragma unroll
        for (int i = 0; i < 4; i++) {
            int f = tid + i * NT, row = f >> 4, seg = f & 15;
            float4* p = (float4*)(sm + OXS + row * 72 + seg * 4);
            float4 v = *p;
            *p = make_float4(tf32f(v.x), tf32f(v.y), tf32f(v.z), tf32f(v.w));
        }
    }
    __syncthreads();

    float acc2[2][2][4];
    #pragma unroll
    for (int m = 0; m < 2; m++)
        #pragma unroll
        for (int n = 0; n < 2; n++)
            #pragma unroll
            for (int q = 0; q < 4; q++) acc2[m][n][q] = 0.f;

    #pragma unroll 1
    for (int it = 0; it < 8; it++) {
        const int   e    = (it < 4) ? e0 : e1;
        const int   j    = it & 3;
        const float gate = (it < 4) ? g0 : g1;

        // ---- prefetch W1(it+1) + W2(it) into idle buffer halves ----
        if (it < 7) {
            const int en = (it + 1 >= 4) ? e1 : e0;
            const int jn = (it + 1) & 3;
            const float* w1s = sW1 + (size_t)(en * 4 + jn) * 8192;
            const uint32_t dst = OW1 + ((it + 1) & 1) * 8704;
            #pragma unroll
            for (int i = 0; i < 4; i++) {
                int f = tid + i * NT, row = f >> 5, seg = f & 31;
                CPA16(smb + (dst + row * 136 + seg * 4) * 4, w1s + row * 128 + seg * 4);
            }
        }
        {
            const float* w2s = sW2 + (size_t)(e * 4 + j) * 8192;
            const uint32_t dst = OW2 + (it & 1) * 9216;
            #pragma unroll
            for (int i = 0; i < 4; i++) {
                int f = tid + i * NT, row = f >> 4, seg = f & 15;
                CPA16(smb + (dst + row * 72 + seg * 4) * 4, w2s + row * 64 + seg * 4);
            }
        }
        CPA_COMMIT();

        const float bia0 = __ldg(b1 + e * CHID + j * 64 + wm * 16 + g);
        const float bia1 = __ldg(b1 + e * CHID + j * 64 + wm * 16 + 8 + g);

        // ---- GEMM1(it): D1[64ch][64px], warp tile 16x16 ----
        float acc1[2][4];
        #pragma unroll
        for (int n = 0; n < 2; n++)
            #pragma unroll
            for (int q = 0; q < 4; q++) acc1[n][q] = 0.f;
        {
            const float* w1b = sm + OW1 + (it & 1) * 8704;
            #pragma unroll 8
            for (int k = 0; k < 16; k++) {
                float2 aA = *(const float2*)(w1b + (wm * 16 + g) * 136 + 8 * k + 2 * t);
                float2 aB = *(const float2*)(w1b + (wm * 16 + 8 + g) * 136 + 8 * k + 2 * t);
                float a[4] = {aA.x, aB.x, aA.y, aB.y};
                #pragma unroll
                for (int ni = 0; ni < 2; ni++) {
                    int px = wn * 16 + 8 * ni + g;
                    float b0v = sm[OXS + (8 * k + t) * 72 + px];
                    float b1v = sm[OXS + (8 * k + t + 4) * 72 + px];
                    mma8(acc1[ni], a, b0v, b1v);
                }
            }
        }

        // ---- GEMM2(it-1): D2[128oc][64px], warp tile 32x16 ----
        if (it > 0) {
            const float* w2b = sm + OW2 + ((it - 1) & 1) * 9216;
            const float* hb  = sm + OHS + ((it - 1) & 1) * 4608;
            #pragma unroll
            for (int k = 0; k < 8; k++) {
                float a[2][4];
                #pragma unroll
                for (int mi = 0; mi < 2; mi++) {
                    int R = wm * 32 + 16 * mi;
                    float2 aA = *(const float2*)(w2b + (R + g) * 72 + 8 * k + 2 * t);
                    float2 aB = *(const float2*)(w2b + (R + 8 + g) * 72 + 8 * k + 2 * t);
                    a[mi][0] = aA.x; a[mi][1] = aB.x; a[mi][2] = aA.y; a[mi][3] = aB.y;
                }
                #pragma unroll
                for (int ni = 0; ni < 2; ni++) {
                    int px = wn * 16 + 8 * ni + g;
                    float b0v = hb[(8 * k + t) * 72 + px];
                    float b1v = hb[(8 * k + t + 4) * 72 + px];
                    mma8(acc2[0][ni], a[0], b0v, b1v);
                    mma8(acc2[1][ni], a[1], b0v, b1v);
                }
            }
        }

        // ---- epilogue: bias + SiLU + gate -> h[it&1] ----
        {
            float* hb = sm + OHS + (it & 1) * 4608;
            int ch = wm * 16 + g;
            #pragma unroll
            for (int ni = 0; ni < 2; ni++) {
                int px = wn * 16 + 8 * ni + 2 * t;
                float v0 = acc1[ni][0] + bia0;
                float v1 = acc1[ni][1] + bia0;
                float v2 = acc1[ni][2] + bia1;
                float v3 = acc1[ni][3] + bia1;
                float h0 = gate * (v0 / (1.f + __expf(-v0)));
                float h1 = gate * (v1 / (1.f + __expf(-v1)));
                float h2 = gate * (v2 / (1.f + __expf(-v2)));
                float h3 = gate * (v3 / (1.f + __expf(-v3)));
                *(float2*)(hb + ch * 72 + px)       = make_float2(tf32f(h0), tf32f(h1));
                *(float2*)(hb + (ch + 8) * 72 + px) = make_float2(tf32f(h2), tf32f(h3));
            }
        }

        CPA_WAIT0();       // prefetched W1(it+1)/W2(it) landed
        __syncthreads();   // h(it) + prefetches visible; old buffers quiesced
    }

    // ---- tail: GEMM2(7) ----
    {
        const float* w2b = sm + OW2 + 9216;   // buf 1 (7&1)
        const float* hb  = sm + OHS + 4608;
        #pragma unroll
        for (int k = 0; k < 8; k++) {
            float a[2][4];
            #pragma unroll
            for (int mi = 0; mi < 2; mi++) {
                int R = wm * 32 + 16 * mi;
                float2 aA = *(const float2*)(w2b + (R + g) * 72 + 8 * k + 2 * t);
                float2 aB = *(const float2*)(w2b + (R + 8 + g) * 72 + 8 * k + 2 * t);
                a[mi][0] = aA.x; a[mi][1] = aB.x; a[mi][2] = aA.y; a[mi][3] = aB.y;
            }
            #pragma unroll
            for (int ni = 0; ni < 2; ni++) {
                int px = wn * 16 + 8 * ni + g;
                float b0v = hb[(8 * k + t) * 72 + px];
                float b1v = hb[(8 * k + t + 4) * 72 + px];
                mma8(acc2[0][ni], a[0], b0v, b1v);
                mma8(acc2[1][ni], a[1], b0v, b1v);
            }
        }
    }

    // ---- final store: acc2 + gated b2 -> out ----
    {
        float* ob = out + (size_t)b * COUT * HW + p0;
        #pragma unroll
        for (int mi = 0; mi < 2; mi++) {
            int oc = wm * 32 + 16 * mi + g;
            float gba = sm[OGB + oc], gbb = sm[OGB + oc + 8];
            #pragma unroll
            for (int ni = 0; ni < 2; ni++) {
                int px = wn * 16 + 8 * ni + 2 * t;
                *(float2*)(ob + (size_t)oc * HW + px) =
                    make_float2(acc2[mi][ni][0] + gba, acc2[mi][ni][1] + gba);
                *(float2*)(ob + (size_t)(oc + 8) * HW + px) =
                    make_float2(acc2[mi][ni][2] + gbb, acc2[mi][ni][3] + gbb);
            }
        }
    }
}

extern "C" void kernel_launch(void* const* d_in, const int* in_sizes, int n_in,
                              void* d_out, int out_size) {
    const float* x   = (const float*)d_in[0];
    const float* wts = (const float*)d_in[1];
    const int*   idx = (const int*)d_in[2];
    const float* W1  = (const float*)d_in[3];
    const float* b1  = (const float*)d_in[4];
    const float* W2  = (const float*)d_in[5];
    const float* b2  = (const float*)d_in[6];
    float* out = (float*)d_out;
    (void)in_sizes; (void)n_in; (void)out_size;

    prep_idx<<<1, 256>>>(idx);
    prep_w<<<512, 512>>>(W1, W2);

    cudaFuncSetAttribute(moe_tf32, cudaFuncAttributeMaxDynamicSharedMemorySize, SMB);
    dim3 grid(NTILE, 128);
    moe_tf32<<<grid, NT, SMB>>>(x, wts, b1, b2, out);
}

// round 8
// speedup vs baseline: 1.2325x; 1.2325x over previous
#include <cuda_runtime.h>
#include <cstdint>

#define CIN   128
#define CHID  256
#define COUT  128
#define HW    1600
#define TP    128
#define NT    512
#define NTILE 13

// SMEM float offsets (stride 136: B-scalar loads hit 32 distinct banks)
#define OXS 0                        // x [128 c][136]
#define OH0 17408                    // h buf0 [64 ch][136]
#define OH1 26112                    // h buf1
#define OGB 34816                    // gated b2 [128]
#define SMB ((34816 + 128) * 4)      // 139776 B

// weights packed in per-warp fragment order, tf32-rounded (1MB each)
__device__ float2 sW1p[131072];
__device__ float2 sW2p[131072];
__device__ int    g_idx[256];

__device__ __forceinline__ uint32_t smem_u32(const void* p) {
    uint32_t a;
    asm("{ .reg .u64 t; cvta.to.shared.u64 t, %1; cvt.u32.u64 %0, t; }" : "=r"(a) : "l"(p));
    return a;
}
__device__ __forceinline__ float tf32f(float v) {
    uint32_t r;
    asm("cvt.rna.tf32.f32 %0, %1;" : "=r"(r) : "f"(v));
    return __uint_as_float(r);
}
__device__ __forceinline__ void mma8(float (&d)[4], const float (&a)[4], float b0, float b1) {
    asm("mma.sync.aligned.m16n8k8.row.col.f32.tf32.tf32.f32 "
        "{%0,%1,%2,%3}, {%4,%5,%6,%7}, {%8,%9}, {%0,%1,%2,%3};"
        : "+f"(d[0]), "+f"(d[1]), "+f"(d[2]), "+f"(d[3])
        : "r"(__float_as_uint(a[0])), "r"(__float_as_uint(a[1])),
          "r"(__float_as_uint(a[2])), "r"(__float_as_uint(a[3])),
          "r"(__float_as_uint(b0)),  "r"(__float_as_uint(b1)));
}
#define CPA16(dst, src)      asm volatile("cp.async.ca.shared.global [%0], [%1], 16;" :: "r"(dst), "l"(src))
#define CPA16Z(dst, src, sz) asm volatile("cp.async.ca.shared.global [%0], [%1], 16, %2;" :: "r"(dst), "l"(src), "r"(sz))
#define CPA_COMMIT()         asm volatile("cp.async.commit_group;" ::: "memory")
#define CPA_WAIT0()          asm volatile("cp.async.wait_group 0;" ::: "memory")

__global__ void prep_idx(const int* __restrict__ raw) {
    __shared__ int odd_nz;
    if (threadIdx.x == 0) odd_nz = 0;
    __syncthreads();
    if (threadIdx.x < 128) {
        if (raw[2 * threadIdx.x + 1] != 0) atomicAdd(&odd_nz, 1);
    }
    __syncthreads();
    bool is64 = (odd_nz == 0);
    g_idx[threadIdx.x] = is64 ? raw[2 * threadIdx.x] : raw[threadIdx.x];
}

// Pack weights into fragment order.
// sW1p index: ((((e*4+j)*4 + wm)*16 + k)*2 + half)*32 + lane
//   value = (W1[e][j*64 + wm*16 + half*8 + g][8k + t], same row, col 8k+t+4)
// sW2p index: ((((e*4+j)*8 + mb)*8 + k)*2 + half)*32 + lane   (mb = wm*2+mi)
//   value = (W2[e][mb*16 + half*8 + g][j*64 + 8k + t], same row, col +4)
__global__ void prep_w(const float* __restrict__ W1, const float* __restrict__ W2) {
    int tid = blockIdx.x * blockDim.x + threadIdx.x;   // 0..131071
    int lane = tid & 31, g = lane >> 2, t = lane & 3;
    {
        int half = (tid >> 5) & 1, k = (tid >> 6) & 15, wm = (tid >> 10) & 3;
        int j = (tid >> 12) & 3,  e = (tid >> 14) & 7;
        int ch = j * 64 + wm * 16 + half * 8 + g;
        int c  = 8 * k + t;
        const float* s = W1 + (size_t)e * 32768 + (size_t)ch * 128;
        sW1p[tid] = make_float2(tf32f(s[c]), tf32f(s[c + 4]));
    }
    {
        int half = (tid >> 5) & 1, k = (tid >> 6) & 7, mb = (tid >> 9) & 7;
        int j = (tid >> 12) & 3,  e = (tid >> 14) & 7;
        int oc = mb * 16 + half * 8 + g;
        int ch = j * 64 + 8 * k + t;
        const float* s = W2 + (size_t)e * 32768 + (size_t)oc * 256;
        sW2p[tid] = make_float2(tf32f(s[ch]), tf32f(s[ch + 4]));
    }
}

__global__ __launch_bounds__(NT, 1)
void moe_tf32(const float* __restrict__ x,
              const float* __restrict__ gate_w,
              const float* __restrict__ b1,
              const float* __restrict__ b2,
              float* __restrict__ out)
{
    extern __shared__ float sm[];
    const uint32_t smb = smem_u32(sm);
    const int tid  = threadIdx.x;
    const int lane = tid & 31;
    const int warp = tid >> 5;
    const int g    = lane >> 2;
    const int t    = lane & 3;
    const int wm   = warp >> 2;        // ch/oc block
    const int wn   = warp & 3;         // px block of 32
    const int b    = blockIdx.y;
    const int p0   = blockIdx.x * TP;

    const int   e0 = g_idx[b * 2],           e1 = g_idx[b * 2 + 1];
    const float g0 = __ldg(&gate_w[b * 2]);
    const float g1 = __ldg(&gate_w[b * 2 + 1]);

    if (tid < 128)
        sm[OGB + tid] = g0 * __ldg(&b2[e0 * COUT + tid]) + g1 * __ldg(&b2[e1 * COUT + tid]);

    // ---- prologue: cp.async x tile [128 c][128 px] (zfill OOB), round to tf32 ----
    {
        const float* xb = x + (size_t)b * CIN * HW + p0;
        #pragma unroll
        for (int i = 0; i < 8; i++) {
            int f = tid + i * NT, row = f >> 5, seg = f & 31;
            int ok = (p0 + seg * 4 + 3 < HW);
            const float* src = ok ? (xb + (size_t)row * HW + seg * 4) : x;
            CPA16Z(smb + (uint32_t)(OXS + row * 136 + seg * 4) * 4, src, ok ? 16 : 0);
        }
        CPA_COMMIT();
        CPA_WAIT0();
        #pragma unroll
        for (int i = 0; i < 8; i++) {
            int f = tid + i * NT, row = f >> 5, seg = f & 31;
            float4* p = (float4*)(sm + OXS + row * 136 + seg * 4);
            float4 v = *p;
            *p = make_float4(tf32f(v.x), tf32f(v.y), tf32f(v.z), tf32f(v.w));
        }
    }
    __syncthreads();

    float acc2[2][4][4];
    #pragma unroll
    for (int m = 0; m < 2; m++)
        #pragma unroll
        for (int n = 0; n < 4; n++)
            #pragma unroll
            for (int q = 0; q < 4; q++) acc2[m][n][q] = 0.f;

    #pragma unroll 1
    for (int it = 0; it < 8; it++) {
        const int   e    = (it < 4) ? e0 : e1;
        const int   j    = it & 3;
        const float gate = (it < 4) ? g0 : g1;

        // ---- GEMM1(it): D1[64ch][128px]; A = packed W1 (LDG.64), B = x (LDS) ----
        float acc1[4][4];
        #pragma unroll
        for (int n = 0; n < 4; n++)
            #pragma unroll
            for (int q = 0; q < 4; q++) acc1[n][q] = 0.f;
        {
            const float2* pk1 = sW1p + (size_t)(((e * 4 + j) * 4 + wm) * 1024) + lane;
            #pragma unroll
            for (int k = 0; k < 16; k++) {
                float2 aA = __ldg(pk1 + k * 64);
                float2 aB = __ldg(pk1 + k * 64 + 32);
                float a[4] = {aA.x, aB.x, aA.y, aB.y};
                const float* xr0 = sm + OXS + (8 * k + t) * 136 + wn * 32;
                const float* xr1 = xr0 + 4 * 136;
                #pragma unroll
                for (int ni = 0; ni < 4; ni++)
                    mma8(acc1[ni], a, xr0[8 * ni + g], xr1[8 * ni + g]);
            }
        }

        // ---- GEMM2(it-1): D2[128oc][128px]; A = packed W2, B = h[(it-1)&1] ----
        if (it > 0) {
            const int ep = (it - 1 < 4) ? e0 : e1;
            const int jp = (it - 1) & 3;
            const float* hb = sm + ((it - 1) & 1 ? OH1 : OH0);
            const float2* pk2 = sW2p + (size_t)((ep * 4 + jp) * 4096) + lane;
            #pragma unroll
            for (int k = 0; k < 8; k++) {
                float a[2][4];
                #pragma unroll
                for (int mi = 0; mi < 2; mi++) {
                    float2 aA = __ldg(pk2 + (wm * 2 + mi) * 512 + k * 64);
                    float2 aB = __ldg(pk2 + (wm * 2 + mi) * 512 + k * 64 + 32);
                    a[mi][0] = aA.x; a[mi][1] = aB.x; a[mi][2] = aA.y; a[mi][3] = aB.y;
                }
                const float* hr0 = hb + (8 * k + t) * 136 + wn * 32;
                const float* hr1 = hr0 + 4 * 136;
                #pragma unroll
                for (int ni = 0; ni < 4; ni++) {
                    float b0v = hr0[8 * ni + g], b1v = hr1[8 * ni + g];
                    mma8(acc2[0][ni], a[0], b0v, b1v);
                    mma8(acc2[1][ni], a[1], b0v, b1v);
                }
            }
        }

        // ---- epilogue: bias + SiLU + gate -> h[it&1] ----
        {
            const float bia0 = __ldg(b1 + e * CHID + j * 64 + wm * 16 + g);
            const float bia1 = __ldg(b1 + e * CHID + j * 64 + wm * 16 + 8 + g);
            float* hb = sm + ((it & 1) ? OH1 : OH0);
            int ch = wm * 16 + g;
            #pragma unroll
            for (int ni = 0; ni < 4; ni++) {
                int px = wn * 32 + 8 * ni + 2 * t;
                float v0 = acc1[ni][0] + bia0;
                float v1 = acc1[ni][1] + bia0;
                float v2 = acc1[ni][2] + bia1;
                float v3 = acc1[ni][3] + bia1;
                float h0 = gate * (v0 / (1.f + __expf(-v0)));
                float h1 = gate * (v1 / (1.f + __expf(-v1)));
                float h2 = gate * (v2 / (1.f + __expf(-v2)));
                float h3 = gate * (v3 / (1.f + __expf(-v3)));
                *(float2*)(hb + ch * 136 + px)       = make_float2(tf32f(h0), tf32f(h1));
                *(float2*)(hb + (ch + 8) * 136 + px) = make_float2(tf32f(h2), tf32f(h3));
            }
        }
        __syncthreads();   // publish h(it); GEMM2(it-1) complete CTA-wide
    }

    // ---- tail: GEMM2(7) ----
    {
        const float* hb = sm + OH1;
        const float2* pk2 = sW2p + (size_t)((e1 * 4 + 3) * 4096) + lane;
        #pragma unroll
        for (int k = 0; k < 8; k++) {
            float a[2][4];
            #pragma unroll
            for (int mi = 0; mi < 2; mi++) {
                float2 aA = __ldg(pk2 + (wm * 2 + mi) * 512 + k * 64);
                float2 aB = __ldg(pk2 + (wm * 2 + mi) * 512 + k * 64 + 32);
                a[mi][0] = aA.x; a[mi][1] = aB.x; a[mi][2] = aA.y; a[mi][3] = aB.y;
            }
            const float* hr0 = hb + (8 * k + t) * 136 + wn * 32;
            const float* hr1 = hr0 + 4 * 136;
            #pragma unroll
            for (int ni = 0; ni < 4; ni++) {
                float b0v = hr0[8 * ni + g], b1v = hr1[8 * ni + g];
                mma8(acc2[0][ni], a[0], b0v, b1v);
                mma8(acc2[1][ni], a[1], b0v, b1v);
            }
        }
    }

    // ---- final store: acc2 + gated b2 -> out ----
    {
        float* ob = out + (size_t)b * COUT * HW;
        #pragma unroll
        for (int mi = 0; mi < 2; mi++) {
            int oc = wm * 32 + 16 * mi + g;
            float gba = sm[OGB + oc], gbb = sm[OGB + oc + 8];
            #pragma unroll
            for (int ni = 0; ni < 4; ni++) {
                int px = p0 + wn * 32 + 8 * ni + 2 * t;
                if (px < HW) {
                    *(float2*)(ob + (size_t)oc * HW + px) =
                        make_float2(acc2[mi][ni][0] + gba, acc2[mi][ni][1] + gba);
                    *(float2*)(ob + (size_t)(oc + 8) * HW + px) =
                        make_float2(acc2[mi][ni][2] + gbb, acc2[mi][ni][3] + gbb);
                }
            }
        }
    }
}

extern "C" void kernel_launch(void* const* d_in, const int* in_sizes, int n_in,
                              void* d_out, int out_size) {
    const float* x   = (const float*)d_in[0];
    const float* wts = (const float*)d_in[1];
    const int*   idx = (const int*)d_in[2];
    const float* W1  = (const float*)d_in[3];
    const float* b1  = (const float*)d_in[4];
    const float* W2  = (const float*)d_in[5];
    const float* b2  = (const float*)d_in[6];
    float* out = (float*)d_out;
    (void)in_sizes; (void)n_in; (void)out_size;

    prep_idx<<<1, 256>>>(idx);
    prep_w<<<256, 512>>>(W1, W2);

    cudaFuncSetAttribute(moe_tf32, cudaFuncAttributeMaxDynamicSharedMemorySize, SMB);
    dim3 grid(NTILE, 128);
    moe_tf32<<<grid, NT, SMB>>>(x, wts, b1, b2, out);
}

// round 9
// speedup vs baseline: 1.4627x; 1.1868x over previous
#include <cuda_runtime.h>
#include <cstdint>

#define CIN   128
#define CHID  256
#define COUT  128
#define HW    1600
#define TP    64
#define NT    256
#define NTILE 25

// SMEM float offsets (stride 72: B-scalar LDS hit all 32 banks)
#define OXS 0                        // x [128 c][72]
#define OH0 9216                     // h buf0 [64 ch][72]
#define OH1 13824                    // h buf1
#define OGB 18432                    // gated b2 [128]
#define SMB ((18432 + 128) * 4)      // 74240 B -> 2 CTAs/SM

// weights packed in per-warp fragment order, tf32-rounded (1MB each)
__device__ float2 sW1p[131072];
__device__ float2 sW2p[131072];
__device__ int    g_idx[256];

__device__ __forceinline__ uint32_t smem_u32(const void* p) {
    uint32_t a;
    asm("{ .reg .u64 t; cvta.to.shared.u64 t, %1; cvt.u32.u64 %0, t; }" : "=r"(a) : "l"(p));
    return a;
}
__device__ __forceinline__ float tf32f(float v) {
    uint32_t r;
    asm("cvt.rna.tf32.f32 %0, %1;" : "=r"(r) : "f"(v));
    return __uint_as_float(r);
}
__device__ __forceinline__ void mma8(float (&d)[4], const float (&a)[4], float b0, float b1) {
    asm("mma.sync.aligned.m16n8k8.row.col.f32.tf32.tf32.f32 "
        "{%0,%1,%2,%3}, {%4,%5,%6,%7}, {%8,%9}, {%0,%1,%2,%3};"
        : "+f"(d[0]), "+f"(d[1]), "+f"(d[2]), "+f"(d[3])
        : "r"(__float_as_uint(a[0])), "r"(__float_as_uint(a[1])),
          "r"(__float_as_uint(a[2])), "r"(__float_as_uint(a[3])),
          "r"(__float_as_uint(b0)),  "r"(__float_as_uint(b1)));
}
#define CPA16(dst, src) asm volatile("cp.async.ca.shared.global [%0], [%1], 16;" :: "r"(dst), "l"(src))
#define CPA_COMMIT()    asm volatile("cp.async.commit_group;" ::: "memory")
#define CPA_WAIT0()     asm volatile("cp.async.wait_group 0;" ::: "memory")

__global__ void prep_idx(const int* __restrict__ raw) {
    __shared__ int odd_nz;
    if (threadIdx.x == 0) odd_nz = 0;
    __syncthreads();
    if (threadIdx.x < 128) {
        if (raw[2 * threadIdx.x + 1] != 0) atomicAdd(&odd_nz, 1);
    }
    __syncthreads();
    bool is64 = (odd_nz == 0);
    g_idx[threadIdx.x] = is64 ? raw[2 * threadIdx.x] : raw[threadIdx.x];
}

// Pack weights into per-warp fragment order (same layout as R8).
__global__ void prep_w(const float* __restrict__ W1, const float* __restrict__ W2) {
    int tid = blockIdx.x * blockDim.x + threadIdx.x;   // 0..131071
    int lane = tid & 31, g = lane >> 2, t = lane & 3;
    {
        int half = (tid >> 5) & 1, k = (tid >> 6) & 15, wm = (tid >> 10) & 3;
        int j = (tid >> 12) & 3,  e = (tid >> 14) & 7;
        int ch = j * 64 + wm * 16 + half * 8 + g;
        int c  = 8 * k + t;
        const float* s = W1 + (size_t)e * 32768 + (size_t)ch * 128;
        sW1p[tid] = make_float2(tf32f(s[c]), tf32f(s[c + 4]));
    }
    {
        int half = (tid >> 5) & 1, k = (tid >> 6) & 7, mb = (tid >> 9) & 7;
        int j = (tid >> 12) & 3,  e = (tid >> 14) & 7;
        int oc = mb * 16 + half * 8 + g;
        int ch = j * 64 + 8 * k + t;
        const float* s = W2 + (size_t)e * 32768 + (size_t)oc * 256;
        sW2p[tid] = make_float2(tf32f(s[ch]), tf32f(s[ch + 4]));
    }
}

__global__ __launch_bounds__(NT, 2)
void moe_tf32(const float* __restrict__ x,
              const float* __restrict__ gate_w,
              const float* __restrict__ b1,
              const float* __restrict__ b2,
              float* __restrict__ out)
{
    extern __shared__ float sm[];
    const uint32_t smb = smem_u32(sm);
    const int tid  = threadIdx.x;
    const int lane = tid & 31;
    const int warp = tid >> 5;
    const int g    = lane >> 2;
    const int t    = lane & 3;
    const int wm   = warp >> 1;        // 0..3: ch/oc block
    const int wn   = warp & 1;         // 0..1: px block of 32
    const int b    = blockIdx.y;
    const int p0   = blockIdx.x * TP;

    const int   e0 = g_idx[b * 2],           e1 = g_idx[b * 2 + 1];
    const float g0 = __ldg(&gate_w[b * 2]);
    const float g1 = __ldg(&gate_w[b * 2 + 1]);

    if (tid < 128)
        sm[OGB + tid] = g0 * __ldg(&b2[e0 * COUT + tid]) + g1 * __ldg(&b2[e1 * COUT + tid]);

    // ---- prologue: cp.async x tile [128 c][64 px] (no OOB: 64 | 1600), round ----
    {
        const float* xb = x + (size_t)b * CIN * HW + p0;
        #pragma unroll
        for (int i = 0; i < 8; i++) {
            int f = tid + i * NT, row = f >> 4, seg = f & 15;
            CPA16(smb + (uint32_t)(OXS + row * 72 + seg * 4) * 4,
                  xb + (size_t)row * HW + seg * 4);
        }
        CPA_COMMIT();
        CPA_WAIT0();
        #pragma unroll
        for (int i = 0; i < 8; i++) {
            int f = tid + i * NT, row = f >> 4, seg = f & 15;
            float4* p = (float4*)(sm + OXS + row * 72 + seg * 4);
            float4 v = *p;
            *p = make_float4(tf32f(v.x), tf32f(v.y), tf32f(v.z), tf32f(v.w));
        }
    }
    __syncthreads();

    float acc2[2][4][4];
    #pragma unroll
    for (int m = 0; m < 2; m++)
        #pragma unroll
        for (int n = 0; n < 4; n++)
            #pragma unroll
            for (int q = 0; q < 4; q++) acc2[m][n][q] = 0.f;

    #pragma unroll 1
    for (int it = 0; it < 8; it++) {
        const int   e    = (it < 4) ? e0 : e1;
        const int   j    = it & 3;
        const float gate = (it < 4) ? g0 : g1;

        // ---- GEMM1(it): D1[64ch][64px]; A = packed W1 (LDG.64, depth-1 pipelined) ----
        float acc1[4][4];
        #pragma unroll
        for (int n = 0; n < 4; n++)
            #pragma unroll
            for (int q = 0; q < 4; q++) acc1[n][q] = 0.f;
        {
            const float2* pk1 = sW1p + (size_t)(((e * 4 + j) * 4 + wm) * 1024) + lane;
            float2 aA = __ldg(pk1), aB = __ldg(pk1 + 32);
            #pragma unroll
            for (int k = 0; k < 16; k++) {
                float2 nA, nB;
                if (k < 15) { nA = __ldg(pk1 + (k + 1) * 64); nB = __ldg(pk1 + (k + 1) * 64 + 32); }
                float a[4] = {aA.x, aB.x, aA.y, aB.y};
                const float* xr0 = sm + OXS + (8 * k + t) * 72 + wn * 32;
                const float* xr1 = xr0 + 4 * 72;
                #pragma unroll
                for (int ni = 0; ni < 4; ni++)
                    mma8(acc1[ni], a, xr0[8 * ni + g], xr1[8 * ni + g]);
                aA = nA; aB = nB;
            }
        }

        // ---- GEMM2(it-1): D2[128oc][64px]; A = packed W2 (pipelined), B = h ----
        if (it > 0) {
            const int ep = (it - 1 < 4) ? e0 : e1;
            const int jp = (it - 1) & 3;
            const float* hb = sm + ((it - 1) & 1 ? OH1 : OH0);
            const float2* pk2 = sW2p + (size_t)((ep * 4 + jp) * 4096) + (wm * 2) * 512 + lane;
            float2 aA0 = __ldg(pk2),       aB0 = __ldg(pk2 + 32);
            float2 aA1 = __ldg(pk2 + 512), aB1 = __ldg(pk2 + 512 + 32);
            #pragma unroll
            for (int k = 0; k < 8; k++) {
                float2 nA0, nB0, nA1, nB1;
                if (k < 7) {
                    nA0 = __ldg(pk2 + (k + 1) * 64);       nB0 = __ldg(pk2 + (k + 1) * 64 + 32);
                    nA1 = __ldg(pk2 + 512 + (k + 1) * 64); nB1 = __ldg(pk2 + 512 + (k + 1) * 64 + 32);
                }
                float a0[4] = {aA0.x, aB0.x, aA0.y, aB0.y};
                float a1[4] = {aA1.x, aB1.x, aA1.y, aB1.y};
                const float* hr0 = hb + (8 * k + t) * 72 + wn * 32;
                const float* hr1 = hr0 + 4 * 72;
                #pragma unroll
                for (int ni = 0; ni < 4; ni++) {
                    float b0v = hr0[8 * ni + g], b1v = hr1[8 * ni + g];
                    mma8(acc2[0][ni], a0, b0v, b1v);
                    mma8(acc2[1][ni], a1, b0v, b1v);
                }
                aA0 = nA0; aB0 = nB0; aA1 = nA1; aB1 = nB1;
            }
        }

        // ---- epilogue: bias + SiLU + gate -> h[it&1] ----
        {
            const float bia0 = __ldg(b1 + e * CHID + j * 64 + wm * 16 + g);
            const float bia1 = __ldg(b1 + e * CHID + j * 64 + wm * 16 + 8 + g);
            float* hb = sm + ((it & 1) ? OH1 : OH0);
            int ch = wm * 16 + g;
            #pragma unroll
            for (int ni = 0; ni < 4; ni++) {
                int px = wn * 32 + 8 * ni + 2 * t;
                float v0 = acc1[ni][0] + bia0;
                float v1 = acc1[ni][1] + bia0;
                float v2 = acc1[ni][2] + bia1;
                float v3 = acc1[ni][3] + bia1;
                float h0 = gate * (v0 / (1.f + __expf(-v0)));
                float h1 = gate * (v1 / (1.f + __expf(-v1)));
                float h2 = gate * (v2 / (1.f + __expf(-v2)));
                float h3 = gate * (v3 / (1.f + __expf(-v3)));
                *(float2*)(hb + ch * 72 + px)       = make_float2(tf32f(h0), tf32f(h1));
                *(float2*)(hb + (ch + 8) * 72 + px) = make_float2(tf32f(h2), tf32f(h3));
            }
        }
        __syncthreads();   // publish h(it); GEMM2(it-1) complete CTA-wide
    }

    // ---- tail: GEMM2(7) ----
    {
        const float* hb = sm + OH1;
        const float2* pk2 = sW2p + (size_t)((e1 * 4 + 3) * 4096) + (wm * 2) * 512 + lane;
        #pragma unroll
        for (int k = 0; k < 8; k++) {
            float a[2][4];
            #pragma unroll
            for (int mi = 0; mi < 2; mi++) {
                float2 aA = __ldg(pk2 + mi * 512 + k * 64);
                float2 aB = __ldg(pk2 + mi * 512 + k * 64 + 32);
                a[mi][0] = aA.x; a[mi][1] = aB.x; a[mi][2] = aA.y; a[mi][3] = aB.y;
            }
            const float* hr0 = hb + (8 * k + t) * 72 + wn * 32;
            const float* hr1 = hr0 + 4 * 72;
            #pragma unroll
            for (int ni = 0; ni < 4; ni++) {
                float b0v = hr0[8 * ni + g], b1v = hr1[8 * ni + g];
                mma8(acc2[0][ni], a[0], b0v, b1v);
                mma8(acc2[1][ni], a[1], b0v, b1v);
            }
        }
    }

    // ---- final store: acc2 + gated b2 -> out (no OOB: 64 | 1600) ----
    {
        float* ob = out + (size_t)b * COUT * HW + p0;
        #pragma unroll
        for (int mi = 0; mi < 2; mi++) {
            int oc = wm * 32 + 16 * mi + g;
            float gba = sm[OGB + oc], gbb = sm[OGB + oc + 8];
            #pragma unroll
            for (int ni = 0; ni < 4; ni++) {
                int px = wn * 32 + 8 * ni + 2 * t;
                *(float2*)(ob + (size_t)oc * HW + px) =
                    make_float2(acc2[mi][ni][0] + gba, acc2[mi][ni][1] + gba);
                *(float2*)(ob + (size_t)(oc + 8) * HW + px) =
                    make_float2(acc2[mi][ni][2] + gbb, acc2[mi][ni][3] + gbb);
            }
        }
    }
}

extern "C" void kernel_launch(void* const* d_in, const int* in_sizes, int n_in,
                              void* d_out, int out_size) {
    const float* x   = (const float*)d_in[0];
    const float* wts = (const float*)d_in[1];
    const int*   idx = (const int*)d_in[2];
    const float* W1  = (const float*)d_in[3];
    const float* b1  = (const float*)d_in[4];
    const float* W2  = (const float*)d_in[5];
    const float* b2  = (const float*)d_in[6];
    float* out = (float*)d_out;
    (void)in_sizes; (void)n_in; (void)out_size;

    prep_idx<<<1, 256>>>(idx);
    prep_w<<<256, 512>>>(W1, W2);

    cudaFuncSetAttribute(moe_tf32, cudaFuncAttributeMaxDynamicSharedMemorySize, SMB);
    dim3 grid(NTILE, 128);
    moe_tf32<<<grid, NT, SMB>>>(x, wts, b1, b2, out);
}

// round 10
// speedup vs baseline: 1.4797x; 1.0116x over previous
#include <cuda_runtime.h>
#include <cstdint>

#define CIN   128
#define CHID  256
#define COUT  128
#define HW    1600
#define TP    64
#define NT    256
#define NTILE 25

// SMEM float offsets
#define OXS 0                        // x [128 c][72]  (stride 72: conflict-free scalar LDS)
#define OHB 9216                     // h: 2 halves x 2 bufs x [64 ch][36]
#define HSZ 2304                     // 64*36
#define OGB 18432                    // gated b2 [128]
#define SMB ((18432 + 128) * 4)      // 74240 B -> 2 CTAs/SM

// weights packed in per-warp fragment order, tf32-rounded (1MB each)
__device__ float2 sW1p[131072];
__device__ float2 sW2p[131072];
__device__ int    g_idx[256];

__device__ __forceinline__ uint32_t smem_u32(const void* p) {
    uint32_t a;
    asm("{ .reg .u64 t; cvta.to.shared.u64 t, %1; cvt.u32.u64 %0, t; }" : "=r"(a) : "l"(p));
    return a;
}
__device__ __forceinline__ float tf32f(float v) {
    uint32_t r;
    asm("cvt.rna.tf32.f32 %0, %1;" : "=r"(r) : "f"(v));
    return __uint_as_float(r);
}
__device__ __forceinline__ void mma8(float (&d)[4], const float (&a)[4], float b0, float b1) {
    asm("mma.sync.aligned.m16n8k8.row.col.f32.tf32.tf32.f32 "
        "{%0,%1,%2,%3}, {%4,%5,%6,%7}, {%8,%9}, {%0,%1,%2,%3};"
        : "+f"(d[0]), "+f"(d[1]), "+f"(d[2]), "+f"(d[3])
        : "r"(__float_as_uint(a[0])), "r"(__float_as_uint(a[1])),
          "r"(__float_as_uint(a[2])), "r"(__float_as_uint(a[3])),
          "r"(__float_as_uint(b0)),  "r"(__float_as_uint(b1)));
}
#define CPA16(dst, src) asm volatile("cp.async.ca.shared.global [%0], [%1], 16;" :: "r"(dst), "l"(src))
#define CPA_COMMIT()    asm volatile("cp.async.commit_group;" ::: "memory")
#define CPA_WAIT0()     asm volatile("cp.async.wait_group 0;" ::: "memory")
#define HBAR(id)        asm volatile("bar.sync %0, 128;" :: "r"(id) : "memory")

__global__ void prep_idx(const int* __restrict__ raw) {
    __shared__ int odd_nz;
    if (threadIdx.x == 0) odd_nz = 0;
    __syncthreads();
    if (threadIdx.x < 128) {
        if (raw[2 * threadIdx.x + 1] != 0) atomicAdd(&odd_nz, 1);
    }
    __syncthreads();
    bool is64 = (odd_nz == 0);
    g_idx[threadIdx.x] = is64 ? raw[2 * threadIdx.x] : raw[threadIdx.x];
}

// Pack weights into per-warp fragment order (layout identical to R8/R9).
__global__ void prep_w(const float* __restrict__ W1, const float* __restrict__ W2) {
    int tid = blockIdx.x * blockDim.x + threadIdx.x;   // 0..131071
    int lane = tid & 31, g = lane >> 2, t = lane & 3;
    {
        int half = (tid >> 5) & 1, k = (tid >> 6) & 15, wm = (tid >> 10) & 3;
        int j = (tid >> 12) & 3,  e = (tid >> 14) & 7;
        int ch = j * 64 + wm * 16 + half * 8 + g;
        int c  = 8 * k + t;
        const float* s = W1 + (size_t)e * 32768 + (size_t)ch * 128;
        sW1p[tid] = make_float2(tf32f(s[c]), tf32f(s[c + 4]));
    }
    {
        int half = (tid >> 5) & 1, k = (tid >> 6) & 7, mb = (tid >> 9) & 7;
        int j = (tid >> 12) & 3,  e = (tid >> 14) & 7;
        int oc = mb * 16 + half * 8 + g;
        int ch = j * 64 + 8 * k + t;
        const float* s = W2 + (size_t)e * 32768 + (size_t)oc * 256;
        sW2p[tid] = make_float2(tf32f(s[ch]), tf32f(s[ch + 4]));
    }
}

__global__ __launch_bounds__(NT, 2)
void moe_tf32(const float* __restrict__ x,
              const float* __restrict__ gate_w,
              const float* __restrict__ b1,
              const float* __restrict__ b2,
              float* __restrict__ out)
{
    extern __shared__ float sm[];
    const uint32_t smb = smem_u32(sm);
    const int tid  = threadIdx.x;
    const int lane = tid & 31;
    const int warp = tid >> 5;
    const int g    = lane >> 2;
    const int t    = lane & 3;
    const int hf   = warp >> 2;        // half: 0 -> px [0,32), 1 -> px [32,64)
    const int wm   = warp & 3;         // ch/oc block within half
    const int PX0  = hf * 32;
    const int b    = blockIdx.y;
    const int p0   = blockIdx.x * TP;

    const int   e0 = g_idx[b * 2],           e1 = g_idx[b * 2 + 1];
    const float g0 = __ldg(&gate_w[b * 2]);
    const float g1 = __ldg(&gate_w[b * 2 + 1]);

    if (tid < 128)
        sm[OGB + tid] = g0 * __ldg(&b2[e0 * COUT + tid]) + g1 * __ldg(&b2[e1 * COUT + tid]);

    // ---- prologue: cp.async x tile [128 c][64 px], round to tf32 ----
    {
        const float* xb = x + (size_t)b * CIN * HW + p0;
        #pragma unroll
        for (int i = 0; i < 8; i++) {
            int f = tid + i * NT, row = f >> 4, seg = f & 15;
            CPA16(smb + (uint32_t)(OXS + row * 72 + seg * 4) * 4,
                  xb + (size_t)row * HW + seg * 4);
        }
        CPA_COMMIT();
        CPA_WAIT0();
        #pragma unroll
        for (int i = 0; i < 8; i++) {
            int f = tid + i * NT, row = f >> 4, seg = f & 15;
            float4* p = (float4*)(sm + OXS + row * 72 + seg * 4);
            float4 v = *p;
            *p = make_float4(tf32f(v.x), tf32f(v.y), tf32f(v.z), tf32f(v.w));
        }
    }
    __syncthreads();   // x + gated-b2 visible to both halves

    float* const hbuf0 = sm + OHB + hf * 2 * HSZ;
    float* const hbuf1 = hbuf0 + HSZ;

    float acc2[2][4][4];
    #pragma unroll
    for (int m = 0; m < 2; m++)
        #pragma unroll
        for (int n = 0; n < 4; n++)
            #pragma unroll
            for (int q = 0; q < 4; q++) acc2[m][n][q] = 0.f;

    #pragma unroll 1
    for (int it = 0; it < 8; it++) {
        const int   e    = (it < 4) ? e0 : e1;
        const int   j    = it & 3;
        const float gate = (it < 4) ? g0 : g1;

        // ---- GEMM1(it): D1[16ch x 32px] per warp; A = packed W1 (LDG.64 pipelined) ----
        float acc1[4][4];
        #pragma unroll
        for (int n = 0; n < 4; n++)
            #pragma unroll
            for (int q = 0; q < 4; q++) acc1[n][q] = 0.f;
        {
            const float2* pk1 = sW1p + (size_t)(((e * 4 + j) * 4 + wm) * 1024) + lane;
            float2 aA = __ldg(pk1), aB = __ldg(pk1 + 32);
            #pragma unroll
            for (int k = 0; k < 16; k++) {
                float2 nA, nB;
                if (k < 15) { nA = __ldg(pk1 + (k + 1) * 64); nB = __ldg(pk1 + (k + 1) * 64 + 32); }
                float a[4] = {aA.x, aB.x, aA.y, aB.y};
                const float* xr0 = sm + OXS + (8 * k + t) * 72 + PX0;
                const float* xr1 = xr0 + 4 * 72;
                #pragma unroll
                for (int ni = 0; ni < 4; ni++)
                    mma8(acc1[ni], a, xr0[8 * ni + g], xr1[8 * ni + g]);
                aA = nA; aB = nB;
            }
        }

        // ---- GEMM2(it-1): D2[32oc x 32px] per warp; B = h[(it-1)&1] of this half ----
        if (it > 0) {
            const int ep = (it - 1 < 4) ? e0 : e1;
            const int jp = (it - 1) & 3;
            const float* hb = ((it - 1) & 1) ? hbuf1 : hbuf0;
            const float2* pk2 = sW2p + (size_t)((ep * 4 + jp) * 4096) + (wm * 2) * 512 + lane;
            float2 aA0 = __ldg(pk2),       aB0 = __ldg(pk2 + 32);
            float2 aA1 = __ldg(pk2 + 512), aB1 = __ldg(pk2 + 512 + 32);
            #pragma unroll
            for (int k = 0; k < 8; k++) {
                float2 nA0, nB0, nA1, nB1;
                if (k < 7) {
                    nA0 = __ldg(pk2 + (k + 1) * 64);       nB0 = __ldg(pk2 + (k + 1) * 64 + 32);
                    nA1 = __ldg(pk2 + 512 + (k + 1) * 64); nB1 = __ldg(pk2 + 512 + (k + 1) * 64 + 32);
                }
                float a0[4] = {aA0.x, aB0.x, aA0.y, aB0.y};
                float a1[4] = {aA1.x, aB1.x, aA1.y, aB1.y};
                const float* hr0 = hb + (8 * k + t) * 36;
                const float* hr1 = hr0 + 4 * 36;
                #pragma unroll
                for (int ni = 0; ni < 4; ni++) {
                    float b0v = hr0[8 * ni + g], b1v = hr1[8 * ni + g];
                    mma8(acc2[0][ni], a0, b0v, b1v);
                    mma8(acc2[1][ni], a1, b0v, b1v);
                }
                aA0 = nA0; aB0 = nB0; aA1 = nA1; aB1 = nB1;
            }
        }

        // ---- epilogue: bias + SiLU + gate -> h[it&1] (this half) ----
        {
            const float bia0 = __ldg(b1 + e * CHID + j * 64 + wm * 16 + g);
            const float bia1 = __ldg(b1 + e * CHID + j * 64 + wm * 16 + 8 + g);
            float* hb = (it & 1) ? hbuf1 : hbuf0;
            int ch = wm * 16 + g;
            #pragma unroll
            for (int ni = 0; ni < 4; ni++) {
                int px = 8 * ni + 2 * t;
                float v0 = acc1[ni][0] + bia0;
                float v1 = acc1[ni][1] + bia0;
                float v2 = acc1[ni][2] + bia1;
                float v3 = acc1[ni][3] + bia1;
                float h0 = gate * (v0 / (1.f + __expf(-v0)));
                float h1 = gate * (v1 / (1.f + __expf(-v1)));
                float h2 = gate * (v2 / (1.f + __expf(-v2)));
                float h3 = gate * (v3 / (1.f + __expf(-v3)));
                *(float2*)(hb + ch * 36 + px)       = make_float2(tf32f(h0), tf32f(h1));
                *(float2*)(hb + (ch + 8) * 36 + px) = make_float2(tf32f(h2), tf32f(h3));
            }
        }
        HBAR(hf + 1);   // publish h(it) within this 4-warp half only
    }

    // ---- tail: GEMM2(7) ----
    {
        const float* hb = hbuf1;   // 7 & 1
        const float2* pk2 = sW2p + (size_t)((e1 * 4 + 3) * 4096) + (wm * 2) * 512 + lane;
        #pragma unroll
        for (int k = 0; k < 8; k++) {
            float a[2][4];
            #pragma unroll
            for (int mi = 0; mi < 2; mi++) {
                float2 aA = __ldg(pk2 + mi * 512 + k * 64);
                float2 aB = __ldg(pk2 + mi * 512 + k * 64 + 32);
                a[mi][0] = aA.x; a[mi][1] = aB.x; a[mi][2] = aA.y; a[mi][3] = aB.y;
            }
            const float* hr0 = hb + (8 * k + t) * 36;
            const float* hr1 = hr0 + 4 * 36;
            #pragma unroll
            for (int ni = 0; ni < 4; ni++) {
                float b0v = hr0[8 * ni + g], b1v = hr1[8 * ni + g];
                mma8(acc2[0][ni], a[0], b0v, b1v);
                mma8(acc2[1][ni], a[1], b0v, b1v);
            }
        }
    }

    // ---- final store: acc2 + gated b2 -> out ----
    {
        float* ob = out + (size_t)b * COUT * HW + p0 + PX0;
        #pragma unroll
        for (int mi = 0; mi < 2; mi++) {
            int oc = wm * 32 + 16 * mi + g;
            float gba = sm[OGB + oc], gbb = sm[OGB + oc + 8];
            #pragma unroll
            for (int ni = 0; ni < 4; ni++) {
                int px = 8 * ni + 2 * t;
                *(float2*)(ob + (size_t)oc * HW + px) =
                    make_float2(acc2[mi][ni][0] + gba, acc2[mi][ni][1] + gba);
                *(float2*)(ob + (size_t)(oc + 8) * HW + px) =
                    make_float2(acc2[mi][ni][2] + gbb, acc2[mi][ni][3] + gbb);
            }
        }
    }
}

extern "C" void kernel_launch(void* const* d_in, const int* in_sizes, int n_in,
                              void* d_out, int out_size) {
    const float* x   = (const float*)d_in[0];
    const float* wts = (const float*)d_in[1];
    const int*   idx = (const int*)d_in[2];
    const float* W1  = (const float*)d_in[3];
    const float* b1  = (const float*)d_in[4];
    const float* W2  = (const float*)d_in[5];
    const float* b2  = (const float*)d_in[6];
    float* out = (float*)d_out;
    (void)in_sizes; (void)n_in; (void)out_size;

    prep_idx<<<1, 256>>>(idx);
    prep_w<<<256, 512>>>(W1, W2);

    cudaFuncSetAttribute(moe_tf32, cudaFuncAttributeMaxDynamicSharedMemorySize, SMB);
    dim3 grid(NTILE, 128);
    moe_tf32<<<grid, NT, SMB>>>(x, wts, b1, b2, out);
}

// round 11
// speedup vs baseline: 1.5090x; 1.0198x over previous
#include <cuda_runtime.h>
#include <cstdint>

#define CIN   128
#define CHID  256
#define COUT  128
#define HW    1600
#define TP    64
#define NT    256
#define NTILE 25

#define SX 72      // x row stride (mod 32 == 8 -> conflict-free paired LDS.64)
#define SH 40      // h row stride (mod 32 == 8)

// SMEM float offsets
#define OXS 0                        // x [128 c][72], columns pair-permuted
#define OHB 9216                     // h: 2 halves x 2 bufs x [64 ch][40]
#define HSZ 2560
#define OGB 19456                    // gated b2 [128]
#define SMB ((19456 + 128) * 4)      // 78336 B -> 2 CTAs/SM

// weights packed in per-warp fragment order, tf32-rounded (1MB each)
__device__ float2 sW1p[131072];
__device__ float2 sW2p[131072];
__device__ int    g_idx[256];

__device__ __forceinline__ float tf32f(float v) {
    uint32_t r;
    asm("cvt.rna.tf32.f32 %0, %1;" : "=r"(r) : "f"(v));
    return __uint_as_float(r);
}
__device__ __forceinline__ void mma8(float (&d)[4], const float (&a)[4], float b0, float b1) {
    asm("mma.sync.aligned.m16n8k8.row.col.f32.tf32.tf32.f32 "
        "{%0,%1,%2,%3}, {%4,%5,%6,%7}, {%8,%9}, {%0,%1,%2,%3};"
        : "+f"(d[0]), "+f"(d[1]), "+f"(d[2]), "+f"(d[3])
        : "r"(__float_as_uint(a[0])), "r"(__float_as_uint(a[1])),
          "r"(__float_as_uint(a[2])), "r"(__float_as_uint(a[3])),
          "r"(__float_as_uint(b0)),  "r"(__float_as_uint(b1)));
}
#define HBAR(id) asm volatile("bar.sync %0, 128;" :: "r"(id) : "memory")

__global__ void prep_idx(const int* __restrict__ raw) {
    __shared__ int odd_nz;
    if (threadIdx.x == 0) odd_nz = 0;
    __syncthreads();
    if (threadIdx.x < 128) {
        if (raw[2 * threadIdx.x + 1] != 0) atomicAdd(&odd_nz, 1);
    }
    __syncthreads();
    bool is64 = (odd_nz == 0);
    g_idx[threadIdx.x] = is64 ? raw[2 * threadIdx.x] : raw[threadIdx.x];
}

// Pack weights into per-warp fragment order (layout identical to R8-R10).
__global__ void prep_w(const float* __restrict__ W1, const float* __restrict__ W2) {
    int tid = blockIdx.x * blockDim.x + threadIdx.x;   // 0..131071
    int lane = tid & 31, g = lane >> 2, t = lane & 3;
    {
        int half = (tid >> 5) & 1, k = (tid >> 6) & 15, wm = (tid >> 10) & 3;
        int j = (tid >> 12) & 3,  e = (tid >> 14) & 7;
        int ch = j * 64 + wm * 16 + half * 8 + g;
        int c  = 8 * k + t;
        const float* s = W1 + (size_t)e * 32768 + (size_t)ch * 128;
        sW1p[tid] = make_float2(tf32f(s[c]), tf32f(s[c + 4]));
    }
    {
        int half = (tid >> 5) & 1, k = (tid >> 6) & 7, mb = (tid >> 9) & 7;
        int j = (tid >> 12) & 3,  e = (tid >> 14) & 7;
        int oc = mb * 16 + half * 8 + g;
        int ch = j * 64 + 8 * k + t;
        const float* s = W2 + (size_t)e * 32768 + (size_t)oc * 256;
        sW2p[tid] = make_float2(tf32f(s[ch]), tf32f(s[ch + 4]));
    }
}

__global__ __launch_bounds__(NT, 2)
void moe_tf32(const float* __restrict__ x,
              const float* __restrict__ gate_w,
              const float* __restrict__ b1,
              const float* __restrict__ b2,
              float* __restrict__ out)
{
    extern __shared__ float sm[];
    const int tid  = threadIdx.x;
    const int lane = tid & 31;
    const int warp = tid >> 5;
    const int g    = lane >> 2;
    const int t    = lane & 3;
    const int hf   = warp >> 2;        // half: 0 -> px [0,32), 1 -> px [32,64)
    const int wm   = warp & 3;         // ch/oc block within half
    const int PX0  = hf * 32;
    const int b    = blockIdx.y;
    const int p0   = blockIdx.x * TP;

    const int   e0 = g_idx[b * 2],           e1 = g_idx[b * 2 + 1];
    const float g0 = __ldg(&gate_w[b * 2]);
    const float g1 = __ldg(&gate_w[b * 2 + 1]);

    if (tid < 128)
        sm[OGB + tid] = g0 * __ldg(&b2[e0 * COUT + tid]) + g1 * __ldg(&b2[e1 * COUT + tid]);

    // ---- prologue: stage x pair-permuted + tf32-rounded ----
    // unit u: c = u>>3, blk = (u>>1)&3 (16-px block), half4 = u&1 (which 4 pairs)
    {
        const float* xb = x + (size_t)b * CIN * HW + p0;
        #pragma unroll
        for (int i = 0; i < 4; i++) {
            int u = tid + i * NT;
            int c = u >> 3, blk = (u >> 1) & 3, h4 = u & 1;
            const float* src = xb + (size_t)c * HW + blk * 16 + h4 * 4;
            float4 lo = *(const float4*)(src);        // px p..p+3   (p = blk*16+h4*4)
            float4 hi = *(const float4*)(src + 8);    // px p+8..p+11
            float* dst = sm + OXS + c * SX + blk * 16 + h4 * 8;
            *(float2*)(dst + 0) = make_float2(tf32f(lo.x), tf32f(hi.x));
            *(float2*)(dst + 2) = make_float2(tf32f(lo.y), tf32f(hi.y));
            *(float2*)(dst + 4) = make_float2(tf32f(lo.z), tf32f(hi.z));
            *(float2*)(dst + 6) = make_float2(tf32f(lo.w), tf32f(hi.w));
        }
    }
    __syncthreads();   // x + gated-b2 visible

    float* const hbuf0 = sm + OHB + hf * 2 * HSZ;
    float* const hbuf1 = hbuf0 + HSZ;

    float acc2[2][4][4];
    #pragma unroll
    for (int m = 0; m < 2; m++)
        #pragma unroll
        for (int n = 0; n < 4; n++)
            #pragma unroll
            for (int q = 0; q < 4; q++) acc2[m][n][q] = 0.f;

    #pragma unroll 1
    for (int it = 0; it < 8; it++) {
        const int   e    = (it < 4) ? e0 : e1;
        const int   j    = it & 3;
        const float gate = (it < 4) ? g0 : g1;

        // ---- GEMM1(it): D1[16ch x 32px]; A = packed W1 (LDG.64 pipelined), B = x (LDS.64 pairs) ----
        float acc1[4][4];
        #pragma unroll
        for (int n = 0; n < 4; n++)
            #pragma unroll
            for (int q = 0; q < 4; q++) acc1[n][q] = 0.f;
        {
            const float2* pk1 = sW1p + (size_t)(((e * 4 + j) * 4 + wm) * 1024) + lane;
            float2 aA = __ldg(pk1), aB = __ldg(pk1 + 32);
            #pragma unroll
            for (int k = 0; k < 16; k++) {
                float2 nA, nB;
                if (k < 15) { nA = __ldg(pk1 + (k + 1) * 64); nB = __ldg(pk1 + (k + 1) * 64 + 32); }
                float a[4] = {aA.x, aB.x, aA.y, aB.y};
                const float* xr0 = sm + OXS + (8 * k + t) * SX + PX0;
                const float* xr1 = xr0 + 4 * SX;
                float2 p00 = *(const float2*)(xr0 + 2 * g);        // (col g, col g+8), blk 0
                float2 p10 = *(const float2*)(xr1 + 2 * g);
                float2 p01 = *(const float2*)(xr0 + 16 + 2 * g);   // blk 1
                float2 p11 = *(const float2*)(xr1 + 16 + 2 * g);
                mma8(acc1[0], a, p00.x, p10.x);
                mma8(acc1[1], a, p00.y, p10.y);
                mma8(acc1[2], a, p01.x, p11.x);
                mma8(acc1[3], a, p01.y, p11.y);
                aA = nA; aB = nB;
            }
        }

        // ---- GEMM2(it-1): D2[32oc x 32px]; B = h[(it-1)&1] (LDS.64 pairs) ----
        if (it > 0) {
            const int ep = (it - 1 < 4) ? e0 : e1;
            const int jp = (it - 1) & 3;
            const float* hb = ((it - 1) & 1) ? hbuf1 : hbuf0;
            const float2* pk2 = sW2p + (size_t)((ep * 4 + jp) * 4096) + (wm * 2) * 512 + lane;
            float2 aA0 = __ldg(pk2),       aB0 = __ldg(pk2 + 32);
            float2 aA1 = __ldg(pk2 + 512), aB1 = __ldg(pk2 + 512 + 32);
            #pragma unroll
            for (int k = 0; k < 8; k++) {
                float2 nA0, nB0, nA1, nB1;
                if (k < 7) {
                    nA0 = __ldg(pk2 + (k + 1) * 64);       nB0 = __ldg(pk2 + (k + 1) * 64 + 32);
                    nA1 = __ldg(pk2 + 512 + (k + 1) * 64); nB1 = __ldg(pk2 + 512 + (k + 1) * 64 + 32);
                }
                float a0[4] = {aA0.x, aB0.x, aA0.y, aB0.y};
                float a1[4] = {aA1.x, aB1.x, aA1.y, aB1.y};
                const float* hr0 = hb + (8 * k + t) * SH;
                const float* hr1 = hr0 + 4 * SH;
                float2 q00 = *(const float2*)(hr0 + 2 * g);
                float2 q10 = *(const float2*)(hr1 + 2 * g);
                float2 q01 = *(const float2*)(hr0 + 16 + 2 * g);
                float2 q11 = *(const float2*)(hr1 + 16 + 2 * g);
                mma8(acc2[0][0], a0, q00.x, q10.x);
                mma8(acc2[1][0], a1, q00.x, q10.x);
                mma8(acc2[0][1], a0, q00.y, q10.y);
                mma8(acc2[1][1], a1, q00.y, q10.y);
                mma8(acc2[0][2], a0, q01.x, q11.x);
                mma8(acc2[1][2], a1, q01.x, q11.x);
                mma8(acc2[0][3], a0, q01.y, q11.y);
                mma8(acc2[1][3], a1, q01.y, q11.y);
                aA0 = nA0; aB0 = nB0; aA1 = nA1; aB1 = nB1;
            }
        }

        // ---- epilogue: bias + SiLU + gate -> h[it&1], pair-permuted cols ----
        {
            const float bia0 = __ldg(b1 + e * CHID + j * 64 + wm * 16 + g);
            const float bia1 = __ldg(b1 + e * CHID + j * 64 + wm * 16 + 8 + g);
            float* hb = (it & 1) ? hbuf1 : hbuf0;
            int ch = wm * 16 + g;
            #pragma unroll
            for (int ni = 0; ni < 4; ni++) {
                // col c0 = 8*ni + 2*t -> loc = (c0&~15) + 4*t + (ni&1); c0+1 -> loc+2
                int loc = (ni >> 1) * 16 + 4 * t + (ni & 1);
                float v0 = acc1[ni][0] + bia0;
                float v1 = acc1[ni][1] + bia0;
                float v2 = acc1[ni][2] + bia1;
                float v3 = acc1[ni][3] + bia1;
                float h0 = gate * (v0 / (1.f + __expf(-v0)));
                float h1 = gate * (v1 / (1.f + __expf(-v1)));
                float h2 = gate * (v2 / (1.f + __expf(-v2)));
                float h3 = gate * (v3 / (1.f + __expf(-v3)));
                hb[ch * SH + loc]           = tf32f(h0);
                hb[ch * SH + loc + 2]       = tf32f(h1);
                hb[(ch + 8) * SH + loc]     = tf32f(h2);
                hb[(ch + 8) * SH + loc + 2] = tf32f(h3);
            }
        }
        HBAR(hf + 1);   // publish h(it) within this 4-warp half
    }

    // ---- tail: GEMM2(7) ----
    {
        const float* hb = hbuf1;
        const float2* pk2 = sW2p + (size_t)((e1 * 4 + 3) * 4096) + (wm * 2) * 512 + lane;
        #pragma unroll
        for (int k = 0; k < 8; k++) {
            float a0[4], a1[4];
            {
                float2 aA = __ldg(pk2 + k * 64), aB = __ldg(pk2 + k * 64 + 32);
                a0[0] = aA.x; a0[1] = aB.x; a0[2] = aA.y; a0[3] = aB.y;
                aA = __ldg(pk2 + 512 + k * 64); aB = __ldg(pk2 + 512 + k * 64 + 32);
                a1[0] = aA.x; a1[1] = aB.x; a1[2] = aA.y; a1[3] = aB.y;
            }
            const float* hr0 = hb + (8 * k + t) * SH;
            const float* hr1 = hr0 + 4 * SH;
            float2 q00 = *(const float2*)(hr0 + 2 * g);
            float2 q10 = *(const float2*)(hr1 + 2 * g);
            float2 q01 = *(const float2*)(hr0 + 16 + 2 * g);
            float2 q11 = *(const float2*)(hr1 + 16 + 2 * g);
            mma8(acc2[0][0], a0, q00.x, q10.x);
            mma8(acc2[1][0], a1, q00.x, q10.x);
            mma8(acc2[0][1], a0, q00.y, q10.y);
            mma8(acc2[1][1], a1, q00.y, q10.y);
            mma8(acc2[0][2], a0, q01.x, q11.x);
            mma8(acc2[1][2], a1, q01.x, q11.x);
            mma8(acc2[0][3], a0, q01.y, q11.y);
            mma8(acc2[1][3], a1, q01.y, q11.y);
        }
    }

    // ---- final store: acc2 + gated b2 -> out ----
    {
        float* ob = out + (size_t)b * COUT * HW + p0 + PX0;
        #pragma unroll
        for (int mi = 0; mi < 2; mi++) {
            int oc = wm * 32 + 16 * mi + g;
            float gba = sm[OGB + oc], gbb = sm[OGB + oc + 8];
            #pragma unroll
            for (int ni = 0; ni < 4; ni++) {
                int px = 8 * ni + 2 * t;
                *(float2*)(ob + (size_t)oc * HW + px) =
                    make_float2(acc2[mi][ni][0] + gba, acc2[mi][ni][1] + gba);
                *(float2*)(ob + (size_t)(oc + 8) * HW + px) =
                    make_float2(acc2[mi][ni][2] + gbb, acc2[mi][ni][3] + gbb);
            }
        }
    }
}

extern "C" void kernel_launch(void* const* d_in, const int* in_sizes, int n_in,
                              void* d_out, int out_size) {
    const float* x   = (const float*)d_in[0];
    const float* wts = (const float*)d_in[1];
    const int*   idx = (const int*)d_in[2];
    const float* W1  = (const float*)d_in[3];
    const float* b1  = (const float*)d_in[4];
    const float* W2  = (const float*)d_in[5];
    const float* b2  = (const float*)d_in[6];
    float* out = (float*)d_out;
    (void)in_sizes; (void)n_in; (void)out_size;

    prep_idx<<<1, 256>>>(idx);
    prep_w<<<256, 512>>>(W1, W2);

    cudaFuncSetAttribute(moe_tf32, cudaFuncAttributeMaxDynamicSharedMemorySize, SMB);
    dim3 grid(NTILE, 128);
    moe_tf32<<<grid, NT, SMB>>>(x, wts, b1, b2, out);
}